// round 3
// baseline (speedup 1.0000x reference)
#include <cuda_runtime.h>
#include <cstdint>
#include <cstddef>
#include <math.h>

#define T_  512
#define B_  64
#define I_  1024
#define H_  1024
#define G4  4096
#define M_  (T_ * B_)   // 32768

// Scratch (static __device__ globals: allocation-free, harness-legal)
__device__ float g_xpre[(size_t)M_ * G4];   // 512 MB: [T*B, 4H] pre-activations
__device__ float g_h[2][B_ * H_];           // ping-pong hidden state
__device__ float g_c[B_ * H_];              // cell state (in-place)

// ---------------------------------------------------------------------------
// init: copy h0, c0 into scratch
// ---------------------------------------------------------------------------
__global__ void init_state(const float* __restrict__ h0,
                           const float* __restrict__ c0) {
    int i = blockIdx.x * blockDim.x + threadIdx.x;
    if (i < B_ * H_) {
        g_h[0][i] = h0[i];
        g_c[i]    = c0[i];
    }
}

// ---------------------------------------------------------------------------
// Phase 1: x_pre = input @ W_ih^T + (b_ih + b_hh)
// A: [M, I] row-major (input flattened, row = t*B+b)
// W: [4H, I] row-major  -> C[m][g] = sum_i A[m][i]*W[g][i]
// Classic 128x128 tile, kc=8, 256 threads, 8x8 per thread.
// ---------------------------------------------------------------------------
__global__ __launch_bounds__(256) void sgemm_xpre(
    const float* __restrict__ A, const float* __restrict__ W,
    const float* __restrict__ bih, const float* __restrict__ bhh)
{
    __shared__ float As[8][128];
    __shared__ float Bs[8][128];

    const int tid = threadIdx.x;
    const int m0 = blockIdx.y * 128;
    const int n0 = blockIdx.x * 128;

    const int lRow = tid >> 1;          // 0..127
    const int lK   = (tid & 1) * 4;     // 0 or 4
    const float* Ap = A + (size_t)(m0 + lRow) * I_ + lK;
    const float* Wp = W + (size_t)(n0 + lRow) * I_ + lK;

    const int ty = tid >> 4;            // 0..15 -> 8 rows each
    const int tx = tid & 15;            // 0..15 -> 8 cols each

    float acc[8][8];
#pragma unroll
    for (int i = 0; i < 8; i++)
#pragma unroll
        for (int j = 0; j < 8; j++) acc[i][j] = 0.f;

    for (int k0 = 0; k0 < I_; k0 += 8) {
        float4 av = *(const float4*)(Ap + k0);
        float4 wv = *(const float4*)(Wp + k0);
        As[lK + 0][lRow] = av.x; As[lK + 1][lRow] = av.y;
        As[lK + 2][lRow] = av.z; As[lK + 3][lRow] = av.w;
        Bs[lK + 0][lRow] = wv.x; Bs[lK + 1][lRow] = wv.y;
        Bs[lK + 2][lRow] = wv.z; Bs[lK + 3][lRow] = wv.w;
        __syncthreads();

#pragma unroll
        for (int k = 0; k < 8; k++) {
            float a[8], b[8];
            *(float4*)&a[0] = *(const float4*)&As[k][ty * 8];
            *(float4*)&a[4] = *(const float4*)&As[k][ty * 8 + 4];
            *(float4*)&b[0] = *(const float4*)&Bs[k][tx * 8];
            *(float4*)&b[4] = *(const float4*)&Bs[k][tx * 8 + 4];
#pragma unroll
            for (int i = 0; i < 8; i++)
#pragma unroll
                for (int j = 0; j < 8; j++)
                    acc[i][j] += a[i] * b[j];
        }
        __syncthreads();
    }

#pragma unroll
    for (int i = 0; i < 8; i++) {
        size_t m = (size_t)(m0 + ty * 8 + i);
        float* Crow = g_xpre + m * G4 + (n0 + tx * 8);
#pragma unroll
        for (int j = 0; j < 8; j++) {
            int n = n0 + tx * 8 + j;
            Crow[j] = acc[i][j] + bih[n] + bhh[n];
        }
    }
}

// ---------------------------------------------------------------------------
// Phase 2: one kernel per timestep.
// Block bx owns j-slice [j0, j0+8) across ALL FOUR gates, i.e. pre columns
// c in [0,32): gate = c>>3, j = j0 + (c&7), W_hh row = gate*H + j0 + (c&7).
// Tile: 64(b) x 32(c), K=1024 in chunks of 32. 256 threads.
// Compute mapping: tb = tid&15 (4 b-rows each, via float4), tc = tid>>4 (2 cols).
// Then gates fused: c_t = f*c + i*g ; h_t = o*tanh(c_t).
// Gate order (source): i, f, o, g  (g = last quarter).
// ---------------------------------------------------------------------------
__global__ __launch_bounds__(256) void lstm_step(
    int t, const float* __restrict__ Whh, float* __restrict__ out)
{
    __shared__ float hs[32][68];   // [k][b], padded for alignment
    __shared__ float ws[32][36];   // [k][c]
    __shared__ float ps[32][65];   // [c][b] raw gemm results

    const int tid = threadIdx.x;
    const int j0  = blockIdx.x * 8;

    const float* hin = g_h[t & 1];

    const int tb = tid & 15;       // b rows: 4*tb .. 4*tb+3
    const int tc = tid >> 4;       // cols:   2*tc, 2*tc+1

    // W_hh load mapping: one float4 per thread per chunk
    const int wc   = tid >> 3;                       // 0..31 (col index c)
    const int wk   = (tid & 7) * 4;                  // k within chunk
    const int wrow = (wc >> 3) * H_ + j0 + (wc & 7); // gate*H + j
    const float* Wp = Whh + (size_t)wrow * H_ + wk;

    float acc[4][2];
#pragma unroll
    for (int r = 0; r < 4; r++) { acc[r][0] = 0.f; acc[r][1] = 0.f; }

    for (int k0 = 0; k0 < H_; k0 += 32) {
        // h tile [64 x 32] transposed into hs[k][b]
#pragma unroll
        for (int q = 0; q < 2; q++) {
            int idx = tid + q * 256;
            int b   = idx >> 3;
            int hk  = (idx & 7) * 4;
            float4 hv = *(const float4*)(hin + (size_t)b * H_ + k0 + hk);
            hs[hk + 0][b] = hv.x; hs[hk + 1][b] = hv.y;
            hs[hk + 2][b] = hv.z; hs[hk + 3][b] = hv.w;
        }
        // W tile [32 x 32] transposed into ws[k][c]
        {
            float4 wv = *(const float4*)(Wp + k0);
            ws[wk + 0][wc] = wv.x; ws[wk + 1][wc] = wv.y;
            ws[wk + 2][wc] = wv.z; ws[wk + 3][wc] = wv.w;
        }
        __syncthreads();

#pragma unroll
        for (int k = 0; k < 32; k++) {
            float4 h4 = *(const float4*)&hs[k][tb * 4];
            float2 w2 = *(const float2*)&ws[k][tc * 2];
            acc[0][0] += h4.x * w2.x;  acc[0][1] += h4.x * w2.y;
            acc[1][0] += h4.y * w2.x;  acc[1][1] += h4.y * w2.y;
            acc[2][0] += h4.z * w2.x;  acc[2][1] += h4.z * w2.y;
            acc[3][0] += h4.w * w2.x;  acc[3][1] += h4.w * w2.y;
        }
        __syncthreads();
    }

    // stash gemm results for cross-thread gate combine
#pragma unroll
    for (int r = 0; r < 4; r++)
#pragma unroll
        for (int cc = 0; cc < 2; cc++)
            ps[tc * 2 + cc][tb * 4 + r] = acc[r][cc];
    __syncthreads();

    // gate combine: 512 (b, j) items, 2 per thread
    const float* xp = g_xpre + (size_t)t * B_ * G4;
    float* hout = g_h[(t + 1) & 1];
#pragma unroll
    for (int q = 0; q < 2; q++) {
        int idx = tid + q * 256;
        int j = idx & 7;
        int b = idx >> 3;
        size_t xbase = (size_t)b * G4 + j0 + j;

        float pi = ps[j][b]      + xp[xbase];
        float pf = ps[8 + j][b]  + xp[xbase + H_];
        float po = ps[16 + j][b] + xp[xbase + 2 * H_];
        float pg = ps[24 + j][b] + xp[xbase + 3 * H_];

        float iv = 1.f / (1.f + expf(-pi));
        float fv = 1.f / (1.f + expf(-pf));
        float ov = 1.f / (1.f + expf(-po));
        float gv = tanhf(pg);

        int hidx = b * H_ + j0 + j;
        float ct = fv * g_c[hidx] + iv * gv;
        float ht = ov * tanhf(ct);

        g_c[hidx]  = ct;
        hout[hidx] = ht;
        out[((size_t)t * B_ + b) * H_ + j0 + j] = ht;
    }
}

// ---------------------------------------------------------------------------
// finalize: append h_f, c_f after output[T,B,H].
// 512 steps: step 511 writes g_h[(511+1)&1] = g_h[0].
// ---------------------------------------------------------------------------
__global__ void finalize(float* __restrict__ out) {
    int i = blockIdx.x * blockDim.x + threadIdx.x;
    if (i < B_ * H_) {
        out[(size_t)T_ * B_ * H_ + i]           = g_h[0][i];
        out[(size_t)T_ * B_ * H_ + B_ * H_ + i] = g_c[i];
    }
}

// ---------------------------------------------------------------------------
extern "C" void kernel_launch(void* const* d_in, const int* in_sizes, int n_in,
                              void* d_out, int out_size) {
    const float* input = (const float*)d_in[0];   // [T,B,I]
    const float* h0    = (const float*)d_in[1];   // [1,B,H]
    const float* c0    = (const float*)d_in[2];   // [1,B,H]
    const float* W_ih  = (const float*)d_in[3];   // [4H,I]
    const float* b_ih  = (const float*)d_in[4];   // [4H]
    const float* W_hh  = (const float*)d_in[5];   // [4H,H]
    const float* b_hh  = (const float*)d_in[6];   // [4H]
    float* out = (float*)d_out;

    init_state<<<(B_ * H_ + 255) / 256, 256>>>(h0, c0);

    sgemm_xpre<<<dim3(G4 / 128, M_ / 128), 256>>>(input, W_ih, b_ih, b_hh);

    for (int t = 0; t < T_; t++)
        lstm_step<<<128, 256>>>(t, W_hh, out);

    finalize<<<(B_ * H_ + 255) / 256, 256>>>(out);
}

// round 4
// speedup vs baseline: 1.1722x; 1.1722x over previous
#include <cuda_runtime.h>
#include <cstdint>
#include <cstddef>
#include <math.h>

#define T_  512
#define B_  64
#define I_  1024
#define H_  1024
#define G4  4096
#define M_  (T_ * B_)   // 32768
#define NBLK 128
#define NTHR 256

// ---------------------------------------------------------------------------
// Scratch (__device__ globals: allocation-free, harness-legal)
// ---------------------------------------------------------------------------
__device__ float g_xpre[(size_t)M_ * G4];   // [T*B, 4H] pre-activations
__device__ float g_h[2][B_ * H_];           // ping-pong hidden state (L2 via .cg)
__device__ unsigned g_gen;                  // grid-barrier generation
__device__ unsigned g_arrive;               // grid-barrier arrival counter

// ---------------------------------------------------------------------------
// packed fp32x2 helpers (sm_103a FFMA2 — only reachable via PTX)
// ---------------------------------------------------------------------------
__device__ __forceinline__ void ffma2(unsigned long long& d,
                                      unsigned long long a,
                                      unsigned long long b) {
    asm("fma.rn.f32x2 %0, %1, %2, %0;" : "+l"(d) : "l"(a), "l"(b));
}
__device__ __forceinline__ unsigned long long dup2(float a) {
    unsigned long long r;
    asm("mov.b64 %0, {%1, %1};" : "=l"(r) : "f"(a));
    return r;
}
__device__ __forceinline__ float2 unpk(unsigned long long v) {
    float2 r;
    asm("mov.b64 {%0, %1}, %2;" : "=f"(r.x), "=f"(r.y) : "l"(v));
    return r;
}
__device__ __forceinline__ unsigned ld_acq(unsigned* p) {
    unsigned v;
    asm volatile("ld.acquire.gpu.u32 %0, [%1];" : "=r"(v) : "l"(p) : "memory");
    return v;
}

// ---------------------------------------------------------------------------
__global__ void reset_barrier() {
    g_gen = 0;
    g_arrive = 0;
}

// ---------------------------------------------------------------------------
// Phase 1: x_pre = input @ W_ih^T + (b_ih + b_hh)   (f32x2 inner product)
// 128x128 tile, kc=8, 256 threads, 8x8 per thread (accumulated as 8x4 f32x2).
// ---------------------------------------------------------------------------
__global__ __launch_bounds__(256) void sgemm_xpre(
    const float* __restrict__ A, const float* __restrict__ W,
    const float* __restrict__ bih, const float* __restrict__ bhh)
{
    __shared__ float As[8][128];
    __shared__ float Bs[8][128];

    const int tid = threadIdx.x;
    const int m0 = blockIdx.y * 128;
    const int n0 = blockIdx.x * 128;

    const int lRow = tid >> 1;
    const int lK   = (tid & 1) * 4;
    const float* Ap = A + (size_t)(m0 + lRow) * I_ + lK;
    const float* Wp = W + (size_t)(n0 + lRow) * I_ + lK;

    const int ty = tid >> 4;            // 8 rows each
    const int tx = tid & 15;            // 8 cols each (4 f32x2 pairs)

    unsigned long long acc[8][4];
#pragma unroll
    for (int i = 0; i < 8; i++)
#pragma unroll
        for (int j = 0; j < 4; j++) acc[i][j] = 0ull;

    for (int k0 = 0; k0 < I_; k0 += 8) {
        float4 av = *(const float4*)(Ap + k0);
        float4 wv = *(const float4*)(Wp + k0);
        As[lK + 0][lRow] = av.x; As[lK + 1][lRow] = av.y;
        As[lK + 2][lRow] = av.z; As[lK + 3][lRow] = av.w;
        Bs[lK + 0][lRow] = wv.x; Bs[lK + 1][lRow] = wv.y;
        Bs[lK + 2][lRow] = wv.z; Bs[lK + 3][lRow] = wv.w;
        __syncthreads();

#pragma unroll
        for (int k = 0; k < 8; k++) {
            float a[8];
            *(float4*)&a[0] = *(const float4*)&As[k][ty * 8];
            *(float4*)&a[4] = *(const float4*)&As[k][ty * 8 + 4];
            ulonglong2 b01 = *(const ulonglong2*)&Bs[k][tx * 8];
            ulonglong2 b23 = *(const ulonglong2*)&Bs[k][tx * 8 + 4];
#pragma unroll
            for (int i = 0; i < 8; i++) {
                unsigned long long aa = dup2(a[i]);
                ffma2(acc[i][0], aa, b01.x);
                ffma2(acc[i][1], aa, b01.y);
                ffma2(acc[i][2], aa, b23.x);
                ffma2(acc[i][3], aa, b23.y);
            }
        }
        __syncthreads();
    }

#pragma unroll
    for (int i = 0; i < 8; i++) {
        size_t m = (size_t)(m0 + ty * 8 + i);
        float* Crow = g_xpre + m * G4 + (n0 + tx * 8);
#pragma unroll
        for (int jp = 0; jp < 4; jp++) {
            float2 v = unpk(acc[i][jp]);
            int n = n0 + tx * 8 + 2 * jp;
            Crow[2 * jp + 0] = v.x + bih[n] + bhh[n];
            Crow[2 * jp + 1] = v.y + bih[n + 1] + bhh[n + 1];
        }
    }
}

// ---------------------------------------------------------------------------
// Phase 2: persistent scan kernel. 128 CTAs (1/SM), 256 threads.
// CTA bx owns j-slice [j0, j0+8) across all 4 gates (32 pre columns).
// W_hh slice (32 x 1024 fp32 = 128.5 KB padded) lives in SMEM for all 512
// steps. h ping-pongs via L2 (ld.cg/st.cg). c lives in registers.
// GEMM: warp grid 4(b) x 2(c); thread tile 4b x 2c; f32x2 pairing over k.
// ---------------------------------------------------------------------------
#define WS_PITCH 1028            // 1024 + 4 pad
#define HS_PITCH 132             // 128 + 4 pad
#define PS_PITCH 68
#define SMEM_BYTES ((32 * WS_PITCH + 64 * HS_PITCH + 32 * PS_PITCH) * 4)

__device__ __forceinline__ void grid_barrier(unsigned target) {
    __syncthreads();
    if (threadIdx.x == 0) {
        __threadfence();
        unsigned prev = atomicAdd(&g_arrive, 1u);
        if (prev == NBLK - 1) {
            atomicExch(&g_arrive, 0u);
            __threadfence();
            atomicAdd(&g_gen, 1u);
        } else {
            while (ld_acq(&g_gen) < target) { }
        }
    }
    __syncthreads();
}

__global__ __launch_bounds__(NTHR, 1) void lstm_scan(
    const float* __restrict__ Whh,
    const float* __restrict__ h0,
    const float* __restrict__ c0,
    float* __restrict__ out)
{
    extern __shared__ float smem[];
    float* ws = smem;                       // [32][WS_PITCH]
    float* hs = ws + 32 * WS_PITCH;         // [64][HS_PITCH]
    float* ps = hs + 64 * HS_PITCH;         // [32][PS_PITCH]

    const int tid = threadIdx.x;
    const int j0  = blockIdx.x * 8;

    // --- load resident W_hh slice: column c -> row (c>>3)*H + j0 + (c&7) ---
#pragma unroll
    for (int it = 0; it < 32; it++) {
        int vi = it * 256 + tid;            // 8192 float4s
        int c  = vi >> 8;
        int kv = vi & 255;
        int wrow = (c >> 3) * H_ + j0 + (c & 7);
        *(float4*)&ws[c * WS_PITCH + kv * 4] =
            __ldg((const float4*)(Whh + (size_t)wrow * H_ + kv * 4));
    }

    // --- init state: h0 -> g_h[0] (own slice), c0 -> registers ---
    float creg[2];
#pragma unroll
    for (int q = 0; q < 2; q++) {
        int idx = tid + q * 256;            // 512 (b,j) items
        int j = idx & 7, b = idx >> 3;
        int hidx = b * H_ + j0 + j;
        __stcg(&g_h[0][hidx], h0[hidx]);
        creg[q] = c0[hidx];
    }
    __threadfence();

    // --- compute-thread mapping ---
    const int wid  = tid >> 5, lane = tid & 31;
    const int wb   = wid >> 1;              // 0..3
    const int wc   = wid & 1;               // 0..1
    const int tb4  = lane >> 3;             // 0..3
    const int tc8  = lane & 7;              // 0..7
    const int bloc = wb * 16 + tb4 * 4;     // + r (0..3)
    const int cl0  = wc * 16 + tc8 * 2;     // + cc (0..1)
    const float* wrow0 = ws + cl0 * WS_PITCH;
    const float* wrow1 = ws + (cl0 + 1) * WS_PITCH;

    // h chunk-load mapping (128 k per chunk = 2048 float4s)
    const int hb = (tid * 8) >> 5;          // placeholder, computed per q below

    for (int t = 0; t < T_; t++) {
        grid_barrier((unsigned)(t + 1));    // all h[t] writes visible

        const float* hsrc = g_h[t & 1];
        unsigned long long acc[4][2];
#pragma unroll
        for (int r = 0; r < 4; r++) { acc[r][0] = 0ull; acc[r][1] = 0ull; }

        // prefetch chunk 0
        float4 pf[8];
#pragma unroll
        for (int q = 0; q < 8; q++) {
            int vi = q * 256 + tid;
            int b = vi >> 5, kv = vi & 31;
            pf[q] = __ldcg((const float4*)(hsrc + b * H_ + kv * 4));
        }

        for (int ch = 0; ch < 8; ch++) {
#pragma unroll
            for (int q = 0; q < 8; q++) {
                int vi = q * 256 + tid;
                int b = vi >> 5, kv = vi & 31;
                *(float4*)&hs[b * HS_PITCH + kv * 4] = pf[q];
            }
            __syncthreads();
            if (ch < 7) {
                int base = (ch + 1) * 128;
#pragma unroll
                for (int q = 0; q < 8; q++) {
                    int vi = q * 256 + tid;
                    int b = vi >> 5, kv = vi & 31;
                    pf[q] = __ldcg((const float4*)(hsrc + b * H_ + base + kv * 4));
                }
            }
            const float* w0p = wrow0 + ch * 128;
            const float* w1p = wrow1 + ch * 128;
#pragma unroll 8
            for (int k4 = 0; k4 < 128; k4 += 4) {
                ulonglong2 w0 = *(const ulonglong2*)(w0p + k4);
                ulonglong2 w1 = *(const ulonglong2*)(w1p + k4);
                ulonglong2 hq0 = *(const ulonglong2*)&hs[(bloc + 0) * HS_PITCH + k4];
                ulonglong2 hq1 = *(const ulonglong2*)&hs[(bloc + 1) * HS_PITCH + k4];
                ulonglong2 hq2 = *(const ulonglong2*)&hs[(bloc + 2) * HS_PITCH + k4];
                ulonglong2 hq3 = *(const ulonglong2*)&hs[(bloc + 3) * HS_PITCH + k4];
                ffma2(acc[0][0], hq0.x, w0.x); ffma2(acc[1][0], hq1.x, w0.x);
                ffma2(acc[2][0], hq2.x, w0.x); ffma2(acc[3][0], hq3.x, w0.x);
                ffma2(acc[0][1], hq0.x, w1.x); ffma2(acc[1][1], hq1.x, w1.x);
                ffma2(acc[2][1], hq2.x, w1.x); ffma2(acc[3][1], hq3.x, w1.x);
                ffma2(acc[0][0], hq0.y, w0.y); ffma2(acc[1][0], hq1.y, w0.y);
                ffma2(acc[2][0], hq2.y, w0.y); ffma2(acc[3][0], hq3.y, w0.y);
                ffma2(acc[0][1], hq0.y, w1.y); ffma2(acc[1][1], hq1.y, w1.y);
                ffma2(acc[2][1], hq2.y, w1.y); ffma2(acc[3][1], hq3.y, w1.y);
            }
            __syncthreads();
        }

        // exchange: ps[c][b] = gemm result
#pragma unroll
        for (int r = 0; r < 4; r++)
#pragma unroll
            for (int cc = 0; cc < 2; cc++) {
                float2 v = unpk(acc[r][cc]);
                ps[(cl0 + cc) * PS_PITCH + (bloc + r)] = v.x + v.y;
            }
        __syncthreads();

        // gate combine (order i, f, o, g)
        const float* xp = g_xpre + (size_t)t * B_ * G4;
        float* hout = g_h[(t + 1) & 1];
#pragma unroll
        for (int q = 0; q < 2; q++) {
            int idx = tid + q * 256;
            int j = idx & 7, b = idx >> 3;
            size_t xbase = (size_t)b * G4 + j0 + j;

            float pi = ps[j * PS_PITCH + b]        + __ldg(xp + xbase);
            float pf_ = ps[(8 + j) * PS_PITCH + b] + __ldg(xp + xbase + H_);
            float po = ps[(16 + j) * PS_PITCH + b] + __ldg(xp + xbase + 2 * H_);
            float pg = ps[(24 + j) * PS_PITCH + b] + __ldg(xp + xbase + 3 * H_);

            float iv = 1.f / (1.f + expf(-pi));
            float fv = 1.f / (1.f + expf(-pf_));
            float ov = 1.f / (1.f + expf(-po));
            float gv = tanhf(pg);

            float ct = fv * creg[q] + iv * gv;
            float ht = ov * tanhf(ct);
            creg[q] = ct;

            int hidx = b * H_ + j0 + j;
            __stcg(&hout[hidx], ht);
            out[((size_t)t * B_ + b) * H_ + j0 + j] = ht;
            if (t == T_ - 1) {
                out[(size_t)T_ * B_ * H_ + hidx]           = ht;
                out[(size_t)T_ * B_ * H_ + B_ * H_ + hidx] = ct;
            }
        }
        __threadfence();
        __syncthreads();   // protect hs/ps reuse next iteration
    }
    (void)hb;
}

// ---------------------------------------------------------------------------
extern "C" void kernel_launch(void* const* d_in, const int* in_sizes, int n_in,
                              void* d_out, int out_size) {
    const float* input = (const float*)d_in[0];   // [T,B,I]
    const float* h0    = (const float*)d_in[1];   // [1,B,H]
    const float* c0    = (const float*)d_in[2];   // [1,B,H]
    const float* W_ih  = (const float*)d_in[3];   // [4H,I]
    const float* b_ih  = (const float*)d_in[4];   // [4H]
    const float* W_hh  = (const float*)d_in[5];   // [4H,H]
    const float* b_hh  = (const float*)d_in[6];   // [4H]
    float* out = (float*)d_out;

    static int smem_set = 0;
    if (!smem_set) {
        cudaFuncSetAttribute(lstm_scan,
                             cudaFuncAttributeMaxDynamicSharedMemorySize,
                             SMEM_BYTES);
        smem_set = 1;
    }

    reset_barrier<<<1, 1>>>();
    sgemm_xpre<<<dim3(G4 / 128, M_ / 128), 256>>>(input, W_ih, b_ih, b_hh);
    lstm_scan<<<NBLK, NTHR, SMEM_BYTES>>>(W_hh, h0, c0, out);
}

// round 7
// speedup vs baseline: 2.1834x; 1.8627x over previous
#include <cuda_runtime.h>
#include <cuda_bf16.h>
#include <cstdint>
#include <cstddef>
#include <math.h>

#define T_  512
#define B_  64
#define I_  1024
#define H_  1024
#define G4  4096
#define M_  (T_ * B_)   // 32768
#define NBLK 128
#define NTHR 256

// ---------------------------------------------------------------------------
// Scratch (__device__ globals: allocation-free, harness-legal)
// ---------------------------------------------------------------------------
__device__ float g_xpre[(size_t)M_ * G4];            // [T*B, 4H] pre-activations
__device__ __nv_bfloat16 g_hhi[2][B_ * H_];          // h high bf16 (ping-pong)
__device__ __nv_bfloat16 g_hlo[2][B_ * H_];          // h low  bf16 (ping-pong)
__device__ unsigned g_gen;
__device__ unsigned g_arrive;

// ---------------------------------------------------------------------------
// packed fp32x2 helpers (x_pre GEMM)
// ---------------------------------------------------------------------------
__device__ __forceinline__ void ffma2(unsigned long long& d,
                                      unsigned long long a,
                                      unsigned long long b) {
    asm("fma.rn.f32x2 %0, %1, %2, %0;" : "+l"(d) : "l"(a), "l"(b));
}
__device__ __forceinline__ unsigned long long dup2(float a) {
    unsigned long long r;
    asm("mov.b64 %0, {%1, %1};" : "=l"(r) : "f"(a));
    return r;
}
__device__ __forceinline__ float2 unpk(unsigned long long v) {
    float2 r;
    asm("mov.b64 {%0, %1}, %2;" : "=f"(r.x), "=f"(r.y) : "l"(v));
    return r;
}
__device__ __forceinline__ unsigned ld_acq(unsigned* p) {
    unsigned v;
    asm volatile("ld.acquire.gpu.u32 %0, [%1];" : "=r"(v) : "l"(p) : "memory");
    return v;
}

// ---------------------------------------------------------------------------
// warp-MMA helpers (base-target PTX: sm_80+, compiles for sm_103)
// ---------------------------------------------------------------------------
__device__ __forceinline__ uint32_t smem_u32(const void* p) {
    uint32_t a;
    asm("{ .reg .u64 t; cvta.to.shared.u64 t, %1; cvt.u32.u64 %0, t; }"
        : "=r"(a) : "l"(p));
    return a;
}
__device__ __forceinline__ void ldsm_x4(unsigned* r, uint32_t addr) {
    asm volatile("ldmatrix.sync.aligned.m8n8.x4.shared.b16 {%0,%1,%2,%3}, [%4];"
                 : "=r"(r[0]), "=r"(r[1]), "=r"(r[2]), "=r"(r[3]) : "r"(addr));
}
__device__ __forceinline__ void ldsm_x2(unsigned* r, uint32_t addr) {
    asm volatile("ldmatrix.sync.aligned.m8n8.x2.shared.b16 {%0,%1}, [%2];"
                 : "=r"(r[0]), "=r"(r[1]) : "r"(addr));
}
__device__ __forceinline__ void mma16816(float* c, const unsigned* a,
                                         const unsigned* b) {
    asm volatile("mma.sync.aligned.m16n8k16.row.col.f32.bf16.bf16.f32 "
                 "{%0,%1,%2,%3}, {%4,%5,%6,%7}, {%8,%9}, {%0,%1,%2,%3};"
                 : "+f"(c[0]), "+f"(c[1]), "+f"(c[2]), "+f"(c[3])
                 : "r"(a[0]), "r"(a[1]), "r"(a[2]), "r"(a[3]),
                   "r"(b[0]), "r"(b[1]));
}

// ---------------------------------------------------------------------------
__global__ void reset_barrier() { g_gen = 0; g_arrive = 0; }

__global__ void init_state(const float* __restrict__ h0) {
    int i = blockIdx.x * blockDim.x + threadIdx.x;
    if (i < B_ * H_) {
        float x = h0[i];
        __nv_bfloat16 hi = __float2bfloat16(x);
        __nv_bfloat16 lo = __float2bfloat16(x - __bfloat162float(hi));
        g_hhi[0][i] = hi;
        g_hlo[0][i] = lo;
    }
}

// ---------------------------------------------------------------------------
// Phase 1: x_pre = input @ W_ih^T + (b_ih + b_hh)   (f32x2, proven in R4)
// ---------------------------------------------------------------------------
__global__ __launch_bounds__(256) void sgemm_xpre(
    const float* __restrict__ A, const float* __restrict__ W,
    const float* __restrict__ bih, const float* __restrict__ bhh)
{
    __shared__ float As[8][128];
    __shared__ float Bs[8][128];

    const int tid = threadIdx.x;
    const int m0 = blockIdx.y * 128;
    const int n0 = blockIdx.x * 128;

    const int lRow = tid >> 1;
    const int lK   = (tid & 1) * 4;
    const float* Ap = A + (size_t)(m0 + lRow) * I_ + lK;
    const float* Wp = W + (size_t)(n0 + lRow) * I_ + lK;

    const int ty = tid >> 4;
    const int tx = tid & 15;

    unsigned long long acc[8][4];
#pragma unroll
    for (int i = 0; i < 8; i++)
#pragma unroll
        for (int j = 0; j < 4; j++) acc[i][j] = 0ull;

    for (int k0 = 0; k0 < I_; k0 += 8) {
        float4 av = *(const float4*)(Ap + k0);
        float4 wv = *(const float4*)(Wp + k0);
        As[lK + 0][lRow] = av.x; As[lK + 1][lRow] = av.y;
        As[lK + 2][lRow] = av.z; As[lK + 3][lRow] = av.w;
        Bs[lK + 0][lRow] = wv.x; Bs[lK + 1][lRow] = wv.y;
        Bs[lK + 2][lRow] = wv.z; Bs[lK + 3][lRow] = wv.w;
        __syncthreads();

#pragma unroll
        for (int k = 0; k < 8; k++) {
            float a[8];
            *(float4*)&a[0] = *(const float4*)&As[k][ty * 8];
            *(float4*)&a[4] = *(const float4*)&As[k][ty * 8 + 4];
            ulonglong2 b01 = *(const ulonglong2*)&Bs[k][tx * 8];
            ulonglong2 b23 = *(const ulonglong2*)&Bs[k][tx * 8 + 4];
#pragma unroll
            for (int i = 0; i < 8; i++) {
                unsigned long long aa = dup2(a[i]);
                ffma2(acc[i][0], aa, b01.x);
                ffma2(acc[i][1], aa, b01.y);
                ffma2(acc[i][2], aa, b23.x);
                ffma2(acc[i][3], aa, b23.y);
            }
        }
        __syncthreads();
    }

#pragma unroll
    for (int i = 0; i < 8; i++) {
        size_t m = (size_t)(m0 + ty * 8 + i);
        float* Crow = g_xpre + m * G4 + (n0 + tx * 8);
#pragma unroll
        for (int jp = 0; jp < 4; jp++) {
            float2 v = unpk(acc[i][jp]);
            int n = n0 + tx * 8 + 2 * jp;
            Crow[2 * jp + 0] = v.x + bih[n] + bhh[n];
            Crow[2 * jp + 1] = v.y + bih[n + 1] + bhh[n + 1];
        }
    }
}

// ---------------------------------------------------------------------------
// Phase 2: persistent warp-MMA scan.
// 128 CTAs x 256 thr (8 warps: 4 batch-groups x 2 col-groups).
// CTA owns 32 gate-cols (j-slice of 8 across the 4 gates).
// W slice bf16 hi/lo resident in SMEM, n-major rows of 1024 k (pitch 2064 B).
// Per step: 8 k-chunks of 128; h chunk [64 x 128] bf16 hi/lo prefetched via
// ldcg -> regs -> SMEM (pitch 272 B); split MMA D = Ahi*Bhi + Alo*Bhi + Ahi*Blo.
// Epilogue exchanges 64x32 results via SMEM ps, fuses gates (i,f,o,g),
// c stays in registers, h ping-pongs via L2 (.cg).
// ---------------------------------------------------------------------------
#define W_PITCH_B 2064                 // 1032 bf16
#define A_PITCH_B 272                  // 136 bf16
#define SM_W_HI 0
#define SM_W_LO (SM_W_HI + 32 * W_PITCH_B)          // 66048
#define SM_A_HI (SM_W_LO + 32 * W_PITCH_B)          // 132096
#define SM_A_LO (SM_A_HI + 64 * A_PITCH_B)          // 149504
#define SM_PS   (SM_A_LO + 64 * A_PITCH_B)          // 166912
#define PS_PITCH 68
#define SMEM_NEED (SM_PS + 32 * PS_PITCH * 4)       // 175616
#define SMEM_REQ  (SMEM_NEED + 1024)

__device__ __forceinline__ void grid_barrier(unsigned target) {
    __syncthreads();
    if (threadIdx.x == 0) {
        __threadfence();
        unsigned prev = atomicAdd(&g_arrive, 1u);
        if (prev == NBLK - 1) {
            atomicExch(&g_arrive, 0u);
            __threadfence();
            atomicAdd(&g_gen, 1u);
        } else {
            while (ld_acq(&g_gen) < target) { __nanosleep(64); }
        }
    }
    __syncthreads();
}

__global__ __launch_bounds__(NTHR, 1) void lstm_scan(
    const float* __restrict__ Whh,
    const float* __restrict__ c0,
    float* __restrict__ out)
{
    extern __shared__ char raw[];
    char* sm = (char*)(((uintptr_t)raw + 1023) & ~(uintptr_t)1023);
    const uint32_t sb = smem_u32(sm);

    const int tid  = threadIdx.x;
    const int wid  = tid >> 5;
    const int lane = tid & 31;
    const int j0   = blockIdx.x * 8;

    // --- preload W slice as bf16 hi/lo: row n (0..31) = gate col ---------
    for (int it = 0; it < 128; it++) {
        int e = it * 256 + tid;          // 32768 elements
        int n = e >> 10;
        int k = e & 1023;
        int wrow = (n >> 3) * H_ + j0 + (n & 7);
        float w = __ldg(Whh + (size_t)wrow * H_ + k);
        __nv_bfloat16 hi = __float2bfloat16(w);
        __nv_bfloat16 lo = __float2bfloat16(w - __bfloat162float(hi));
        *(__nv_bfloat16*)(sm + SM_W_HI + n * W_PITCH_B + k * 2) = hi;
        *(__nv_bfloat16*)(sm + SM_W_LO + n * W_PITCH_B + k * 2) = lo;
    }

    // --- c0 into registers: thread owns (b = tid>>2, j = (tid&3)*2 + q) --
    const int cb = tid >> 2;
    const int cj = (tid & 3) * 2;
    float creg[2];
    creg[0] = c0[cb * H_ + j0 + cj];
    creg[1] = c0[cb * H_ + j0 + cj + 1];
    __syncthreads();

    // --- MMA thread mapping ----------------------------------------------
    const int wb = wid & 3;              // batch group (16 rows)
    const int wc = wid >> 2;             // col group (16 cols)
    const int gid = lane >> 2;           // 0..7
    const int tig = lane & 3;            // 0..3

    // ldmatrix A address components
    const uint32_t a_row  = (uint32_t)(wb * 16 + (lane & 15));
    const uint32_t a_kofs = (uint32_t)((lane >> 4) * 8);
    // ldmatrix B address components (lanes 16-31 ignored by .x2; mapped safely)
    const uint32_t b_row0 = (uint32_t)(wc * 16 + (lane & 7));
    const uint32_t b_kofs = (uint32_t)(((lane >> 3) & 1) * 8);

    for (int t = 0; t < T_; t++) {
        grid_barrier((unsigned)(t + 1));

        const __nv_bfloat16* hh = g_hhi[t & 1];
        const __nv_bfloat16* hl = g_hlo[t & 1];

        float acc0[4] = {0.f, 0.f, 0.f, 0.f};
        float acc1[4] = {0.f, 0.f, 0.f, 0.f};

        // prefetch chunk 0 (each thread: 4 hi + 4 lo uint4 segments)
        uint4 pfh[4], pfl[4];
#pragma unroll
        for (int i = 0; i < 4; i++) {
            int s = tid + i * 256;               // 0..1023
            int row = s >> 4, c16 = s & 15;
            size_t goff = (size_t)row * H_ + c16 * 8;
            pfh[i] = __ldcg((const uint4*)(hh + goff));
            pfl[i] = __ldcg((const uint4*)(hl + goff));
        }

        for (int ch = 0; ch < 8; ch++) {
            // stage regs -> SMEM
#pragma unroll
            for (int i = 0; i < 4; i++) {
                int s = tid + i * 256;
                int row = s >> 4, c16 = s & 15;
                uint32_t doff = (uint32_t)(row * A_PITCH_B + c16 * 16);
                *(uint4*)(sm + SM_A_HI + doff) = pfh[i];
                *(uint4*)(sm + SM_A_LO + doff) = pfl[i];
            }
            __syncthreads();
            if (ch < 7) {
                int kbase = (ch + 1) * 128;
#pragma unroll
                for (int i = 0; i < 4; i++) {
                    int s = tid + i * 256;
                    int row = s >> 4, c16 = s & 15;
                    size_t goff = (size_t)row * H_ + kbase + c16 * 8;
                    pfh[i] = __ldcg((const uint4*)(hh + goff));
                    pfl[i] = __ldcg((const uint4*)(hl + goff));
                }
            }

            // compute: 8 k16 sub-chunks
#pragma unroll
            for (int ks = 0; ks < 8; ks++) {
                unsigned ahi[4], alo[4], bh0[2], bh1[2], bl0[2], bl1[2];
                uint32_t ak = (uint32_t)(ks * 16) + a_kofs;
                uint32_t aaddr = sb + SM_A_HI + a_row * A_PITCH_B + ak * 2;
                ldsm_x4(ahi, aaddr);
                ldsm_x4(alo, aaddr + (SM_A_LO - SM_A_HI));

                uint32_t bk = (uint32_t)(ch * 128 + ks * 16) + b_kofs;
                uint32_t baddr0 = sb + SM_W_HI + b_row0 * W_PITCH_B + bk * 2;
                uint32_t baddr1 = baddr0 + 8u * W_PITCH_B;
                ldsm_x2(bh0, baddr0);
                ldsm_x2(bh1, baddr1);
                ldsm_x2(bl0, baddr0 + (SM_W_LO - SM_W_HI));
                ldsm_x2(bl1, baddr1 + (SM_W_LO - SM_W_HI));

                mma16816(acc0, ahi, bh0);
                mma16816(acc1, ahi, bh1);
                mma16816(acc0, alo, bh0);
                mma16816(acc1, alo, bh1);
                mma16816(acc0, ahi, bl0);
                mma16816(acc1, ahi, bl1);
            }
            __syncthreads();
        }

        // --- exchange: ps[col][batch] ------------------------------------
        float* ps = (float*)(sm + SM_PS);
        {
            int c0i = wc * 16 + tig * 2;
            int r0 = wb * 16 + gid;
            ps[(c0i + 0) * PS_PITCH + r0]     = acc0[0];
            ps[(c0i + 1) * PS_PITCH + r0]     = acc0[1];
            ps[(c0i + 0) * PS_PITCH + r0 + 8] = acc0[2];
            ps[(c0i + 1) * PS_PITCH + r0 + 8] = acc0[3];
            int c1i = c0i + 8;
            ps[(c1i + 0) * PS_PITCH + r0]     = acc1[0];
            ps[(c1i + 1) * PS_PITCH + r0]     = acc1[1];
            ps[(c1i + 0) * PS_PITCH + r0 + 8] = acc1[2];
            ps[(c1i + 1) * PS_PITCH + r0 + 8] = acc1[3];
        }
        __syncthreads();

        // --- gate combine: thread owns (cb, cj), (cb, cj+1) --------------
        const float* xp = g_xpre + ((size_t)t * B_ + cb) * G4 + j0;
        float ht2[2];
#pragma unroll
        for (int q = 0; q < 2; q++) {
            int j = cj + q;
            float pi = ps[j * PS_PITCH + cb]        + __ldcs(xp + j);
            float pf = ps[(8 + j) * PS_PITCH + cb]  + __ldcs(xp + j + H_);
            float po = ps[(16 + j) * PS_PITCH + cb] + __ldcs(xp + j + 2 * H_);
            float pg = ps[(24 + j) * PS_PITCH + cb] + __ldcs(xp + j + 3 * H_);

            float iv = 1.f / (1.f + expf(-pi));
            float fv = 1.f / (1.f + expf(-pf));
            float ov = 1.f / (1.f + expf(-po));
            float gv = tanhf(pg);

            float ct = fv * creg[q] + iv * gv;
            float hv = ov * tanhf(ct);
            creg[q] = ct;
            ht2[q] = hv;
        }

        // output (fp32) + next-h (bf16 hi/lo) stores
        *(float2*)(out + ((size_t)t * B_ + cb) * H_ + j0 + cj) =
            make_float2(ht2[0], ht2[1]);

        __nv_bfloat16 h0b = __float2bfloat16(ht2[0]);
        __nv_bfloat16 h1b = __float2bfloat16(ht2[1]);
        __nv_bfloat16 l0b = __float2bfloat16(ht2[0] - __bfloat162float(h0b));
        __nv_bfloat16 l1b = __float2bfloat16(ht2[1] - __bfloat162float(h1b));
        __nv_bfloat162 hp = __halves2bfloat162(h0b, h1b);
        __nv_bfloat162 lp = __halves2bfloat162(l0b, l1b);
        int hoff = cb * H_ + j0 + cj;
        __stcg((unsigned*)(g_hhi[(t + 1) & 1] + hoff),
               *(unsigned*)&hp);
        __stcg((unsigned*)(g_hlo[(t + 1) & 1] + hoff),
               *(unsigned*)&lp);

        if (t == T_ - 1) {
            *(float2*)(out + (size_t)T_ * B_ * H_ + hoff) =
                make_float2(ht2[0], ht2[1]);
            *(float2*)(out + (size_t)T_ * B_ * H_ + B_ * H_ + hoff) =
                make_float2(creg[0], creg[1]);
        }
        __threadfence();
    }
}

// ---------------------------------------------------------------------------
extern "C" void kernel_launch(void* const* d_in, const int* in_sizes, int n_in,
                              void* d_out, int out_size) {
    const float* input = (const float*)d_in[0];   // [T,B,I]
    const float* h0    = (const float*)d_in[1];   // [1,B,H]
    const float* c0    = (const float*)d_in[2];   // [1,B,H]
    const float* W_ih  = (const float*)d_in[3];   // [4H,I]
    const float* b_ih  = (const float*)d_in[4];   // [4H]
    const float* W_hh  = (const float*)d_in[5];   // [4H,H]
    const float* b_hh  = (const float*)d_in[6];   // [4H]
    float* out = (float*)d_out;

    static int smem_set = 0;
    if (!smem_set) {
        cudaFuncSetAttribute(lstm_scan,
                             cudaFuncAttributeMaxDynamicSharedMemorySize,
                             SMEM_REQ);
        smem_set = 1;
    }

    reset_barrier<<<1, 1>>>();
    init_state<<<(B_ * H_ + 255) / 256, 256>>>(h0);
    sgemm_xpre<<<dim3(G4 / 128, M_ / 128), 256>>>(input, W_ih, b_ih, b_hh);
    lstm_scan<<<NBLK, NTHR, SMEM_REQ>>>(W_hh, c0, out);
}

// round 8
// speedup vs baseline: 3.0675x; 1.4049x over previous
#include <cuda_runtime.h>
#include <cuda_bf16.h>
#include <cstdint>
#include <cstddef>
#include <math.h>

#define T_  512
#define B_  64
#define I_  1024
#define H_  1024
#define G4  4096
#define M_  (T_ * B_)   // 32768
#define NBLK 128
#define NTHR 256

// ---------------------------------------------------------------------------
// Scratch (__device__ globals: allocation-free, harness-legal)
// ---------------------------------------------------------------------------
__device__ float g_xpre[(size_t)M_ * G4];            // [T*B, 4H] pre-activations
__device__ __nv_bfloat16 g_hhi[2][B_ * H_];          // h high bf16 (ping-pong)
__device__ __nv_bfloat16 g_hlo[2][B_ * H_];          // h low  bf16 (ping-pong)
__device__ __nv_bfloat16 g_xhi[(size_t)M_ * I_];     // input hi bf16
__device__ __nv_bfloat16 g_xlo[(size_t)M_ * I_];     // input lo bf16
__device__ __nv_bfloat16 g_whi[(size_t)G4 * I_];     // W_ih hi bf16
__device__ __nv_bfloat16 g_wlo[(size_t)G4 * I_];     // W_ih lo bf16
__device__ unsigned g_gen;
__device__ unsigned g_arrive;

__device__ __forceinline__ unsigned ld_acq(unsigned* p) {
    unsigned v;
    asm volatile("ld.acquire.gpu.u32 %0, [%1];" : "=r"(v) : "l"(p) : "memory");
    return v;
}

// ---------------------------------------------------------------------------
// warp-MMA helpers (base-target PTX: sm_80+, compiles for sm_103)
// ---------------------------------------------------------------------------
__device__ __forceinline__ uint32_t smem_u32(const void* p) {
    uint32_t a;
    asm("{ .reg .u64 t; cvta.to.shared.u64 t, %1; cvt.u32.u64 %0, t; }"
        : "=r"(a) : "l"(p));
    return a;
}
__device__ __forceinline__ void ldsm_x4(unsigned* r, uint32_t addr) {
    asm volatile("ldmatrix.sync.aligned.m8n8.x4.shared.b16 {%0,%1,%2,%3}, [%4];"
                 : "=r"(r[0]), "=r"(r[1]), "=r"(r[2]), "=r"(r[3]) : "r"(addr));
}
__device__ __forceinline__ void ldsm_x2(unsigned* r, uint32_t addr) {
    asm volatile("ldmatrix.sync.aligned.m8n8.x2.shared.b16 {%0,%1}, [%2];"
                 : "=r"(r[0]), "=r"(r[1]) : "r"(addr));
}
__device__ __forceinline__ void mma16816(float* c, const unsigned* a,
                                         const unsigned* b) {
    asm volatile("mma.sync.aligned.m16n8k16.row.col.f32.bf16.bf16.f32 "
                 "{%0,%1,%2,%3}, {%4,%5,%6,%7}, {%8,%9}, {%0,%1,%2,%3};"
                 : "+f"(c[0]), "+f"(c[1]), "+f"(c[2]), "+f"(c[3])
                 : "r"(a[0]), "r"(a[1]), "r"(a[2]), "r"(a[3]),
                   "r"(b[0]), "r"(b[1]));
}
__device__ __forceinline__ void cp_async16(uint32_t daddr, const void* src) {
    asm volatile("cp.async.cg.shared.global [%0], [%1], 16;"
                 :: "r"(daddr), "l"(__cvta_generic_to_global(src)));
}
__device__ __forceinline__ void cp_commit() {
    asm volatile("cp.async.commit_group;");
}
template <int N>
__device__ __forceinline__ void cp_wait() {
    asm volatile("cp.async.wait_group %0;" :: "n"(N));
}

// ---------------------------------------------------------------------------
__global__ void reset_barrier() { g_gen = 0; g_arrive = 0; }

__global__ void init_state(const float* __restrict__ h0) {
    int i = blockIdx.x * blockDim.x + threadIdx.x;
    if (i < B_ * H_) {
        float x = h0[i];
        __nv_bfloat16 hi = __float2bfloat16(x);
        __nv_bfloat16 lo = __float2bfloat16(x - __bfloat162float(hi));
        g_hhi[0][i] = hi;
        g_hlo[0][i] = lo;
    }
}

// split fp32 -> bf16 hi/lo (vectorized, grid-stride)
__global__ void cvt_split(const float* __restrict__ src,
                          __nv_bfloat16* __restrict__ hi,
                          __nv_bfloat16* __restrict__ lo, int n4) {
    for (int i = blockIdx.x * blockDim.x + threadIdx.x; i < n4;
         i += gridDim.x * blockDim.x) {
        float4 v = *(const float4*)(src + (size_t)i * 4);
        __nv_bfloat16 h0 = __float2bfloat16(v.x);
        __nv_bfloat16 h1 = __float2bfloat16(v.y);
        __nv_bfloat16 h2 = __float2bfloat16(v.z);
        __nv_bfloat16 h3 = __float2bfloat16(v.w);
        __nv_bfloat162 hp0 = __halves2bfloat162(h0, h1);
        __nv_bfloat162 hp1 = __halves2bfloat162(h2, h3);
        __nv_bfloat162 lp0 = __halves2bfloat162(
            __float2bfloat16(v.x - __bfloat162float(h0)),
            __float2bfloat16(v.y - __bfloat162float(h1)));
        __nv_bfloat162 lp1 = __halves2bfloat162(
            __float2bfloat16(v.z - __bfloat162float(h2)),
            __float2bfloat16(v.w - __bfloat162float(h3)));
        *(uint2*)(hi + (size_t)i * 4) =
            make_uint2(*(unsigned*)&hp0, *(unsigned*)&hp1);
        *(uint2*)(lo + (size_t)i * 4) =
            make_uint2(*(unsigned*)&lp0, *(unsigned*)&lp1);
    }
}

// ---------------------------------------------------------------------------
// Phase 1: x_pre = input @ W_ih^T + (b_ih + b_hh)  via bf16-split HMMA.
// 128x128 tiles, kc=64, 8 warps (4m x 2n), warp tile 32x64.
// cp.async double-buffered stages; 3-term split: Ahi*Bhi + Alo*Bhi + Ahi*Blo.
// ---------------------------------------------------------------------------
#define XPITCH 144                      // 64 bf16 = 128 B + 16 pad (≡16 mod 128)
#define XT_SZ  (128 * XPITCH)           // 18432 per tensor-half
#define XSA_HI 0
#define XSA_LO (1 * XT_SZ)
#define XSW_HI (2 * XT_SZ)
#define XSW_LO (3 * XT_SZ)
#define XBUF   (4 * XT_SZ)              // 73728 per stage
#define XS_BIAS (2 * XBUF)              // 147456
#define XSMEM_REQ (XS_BIAS + 512 + 256) // ~148 KB

__global__ __launch_bounds__(256, 1) void hmma_xpre(
    const float* __restrict__ bih, const float* __restrict__ bhh)
{
    extern __shared__ char xsm[];
    const uint32_t sb = smem_u32(xsm);

    const int tid  = threadIdx.x;
    const int wid  = tid >> 5;
    const int lane = tid & 31;
    const int m0 = blockIdx.y * 128;
    const int n0 = blockIdx.x * 128;

    // bias row for this CTA's 128 cols
    if (tid < 128) {
        ((float*)(xsm + XS_BIAS))[tid] = bih[n0 + tid] + bhh[n0 + tid];
    }

    // chunk load: 4096 x 16B pieces -> 16 per thread
    const int prow = tid >> 1;                 // 0..127
    const int pseg0 = (tid & 1) * 4;           // 0 or 4 (4 segs each)
    auto load_chunk = [&](int kb, int buf) {
        uint32_t base = sb + (uint32_t)buf * XBUF;
        const __nv_bfloat16* ah = g_xhi + (size_t)(m0 + prow) * I_ + kb;
        const __nv_bfloat16* al = g_xlo + (size_t)(m0 + prow) * I_ + kb;
        const __nv_bfloat16* wh = g_whi + (size_t)(n0 + prow) * I_ + kb;
        const __nv_bfloat16* wl = g_wlo + (size_t)(n0 + prow) * I_ + kb;
        uint32_t ro = (uint32_t)prow * XPITCH;
#pragma unroll
        for (int s = 0; s < 4; s++) {
            int seg = pseg0 + s;
            uint32_t so = ro + (uint32_t)seg * 16;
            cp_async16(base + XSA_HI + so, ah + seg * 8);
            cp_async16(base + XSA_LO + so, al + seg * 8);
            cp_async16(base + XSW_HI + so, wh + seg * 8);
            cp_async16(base + XSW_LO + so, wl + seg * 8);
        }
    };

    // MMA lane mappings (identical to the verified scan patterns)
    const int wm = wid & 3;
    const int wn = wid >> 2;
    const uint32_t a_row  = (uint32_t)(wm * 32 + (lane & 15));
    const uint32_t a_kofs = (uint32_t)((lane >> 4) * 8);
    const uint32_t b_col  = (uint32_t)(wn * 64 + ((lane >> 4) << 3) + (lane & 7));
    const uint32_t b_kofs = (uint32_t)(((lane >> 3) & 1) * 8);

    float acc[2][8][4];
#pragma unroll
    for (int i = 0; i < 2; i++)
#pragma unroll
        for (int j = 0; j < 8; j++)
#pragma unroll
            for (int k = 0; k < 4; k++) acc[i][j][k] = 0.f;

    load_chunk(0, 0);
    cp_commit();

    for (int ch = 0; ch < 16; ch++) {
        if (ch < 15) {
            load_chunk((ch + 1) * 64, (ch + 1) & 1);
            cp_commit();
            cp_wait<1>();
        } else {
            cp_wait<0>();
        }
        __syncthreads();

        uint32_t bufb = sb + (uint32_t)(ch & 1) * XBUF;
#pragma unroll
        for (int ks = 0; ks < 4; ks++) {
            unsigned ahi0[4], ahi1[4], alo0[4], alo1[4];
            uint32_t ak = (uint32_t)(ks * 16) + a_kofs;
            uint32_t a0 = bufb + XSA_HI + a_row * XPITCH + ak * 2;
            uint32_t a1 = a0 + 16u * XPITCH;
            ldsm_x4(ahi0, a0);
            ldsm_x4(ahi1, a1);
            ldsm_x4(alo0, a0 + (XSA_LO - XSA_HI));
            ldsm_x4(alo1, a1 + (XSA_LO - XSA_HI));

#pragma unroll
            for (int ng = 0; ng < 4; ng++) {
                unsigned bh[4], bl[4];
                uint32_t bk = (uint32_t)(ks * 16) + b_kofs;
                uint32_t ba = bufb + XSW_HI + (b_col + ng * 16) * XPITCH + bk * 2;
                ldsm_x4(bh, ba);
                ldsm_x4(bl, ba + (XSW_LO - XSW_HI));

                mma16816(acc[0][ng * 2 + 0], ahi0, bh);
                mma16816(acc[0][ng * 2 + 1], ahi0, bh + 2);
                mma16816(acc[1][ng * 2 + 0], ahi1, bh);
                mma16816(acc[1][ng * 2 + 1], ahi1, bh + 2);
                mma16816(acc[0][ng * 2 + 0], alo0, bh);
                mma16816(acc[0][ng * 2 + 1], alo0, bh + 2);
                mma16816(acc[1][ng * 2 + 0], alo1, bh);
                mma16816(acc[1][ng * 2 + 1], alo1, bh + 2);
                mma16816(acc[0][ng * 2 + 0], ahi0, bl);
                mma16816(acc[0][ng * 2 + 1], ahi0, bl + 2);
                mma16816(acc[1][ng * 2 + 0], ahi1, bl);
                mma16816(acc[1][ng * 2 + 1], ahi1, bl + 2);
            }
        }
        __syncthreads();
    }

    // epilogue: bias add + store fp32
    const float* bias = (const float*)(xsm + XS_BIAS);
    const int gid = lane >> 2;
    const int tig = lane & 3;
#pragma unroll
    for (int mi = 0; mi < 2; mi++) {
        int r0 = m0 + wm * 32 + mi * 16 + gid;
#pragma unroll
        for (int f = 0; f < 8; f++) {
            int cl = wn * 64 + f * 8 + tig * 2;
            float b0 = bias[cl], b1 = bias[cl + 1];
            float* p0 = g_xpre + (size_t)r0 * G4 + n0 + cl;
            *(float2*)p0 = make_float2(acc[mi][f][0] + b0, acc[mi][f][1] + b1);
            float* p1 = p0 + (size_t)8 * G4;
            *(float2*)p1 = make_float2(acc[mi][f][2] + b0, acc[mi][f][3] + b1);
        }
    }
}

// ---------------------------------------------------------------------------
// Phase 2: persistent warp-MMA scan.  (byte-identical to the passing R7 kernel)
// ---------------------------------------------------------------------------
#define W_PITCH_B 2064                 // 1032 bf16
#define A_PITCH_B 272                  // 136 bf16
#define SM_W_HI 0
#define SM_W_LO (SM_W_HI + 32 * W_PITCH_B)          // 66048
#define SM_A_HI (SM_W_LO + 32 * W_PITCH_B)          // 132096
#define SM_A_LO (SM_A_HI + 64 * A_PITCH_B)          // 149504
#define SM_PS   (SM_A_LO + 64 * A_PITCH_B)          // 166912
#define PS_PITCH 68
#define SMEM_NEED (SM_PS + 32 * PS_PITCH * 4)       // 175616
#define SMEM_REQ  (SMEM_NEED + 1024)

__device__ __forceinline__ void grid_barrier(unsigned target) {
    __syncthreads();
    if (threadIdx.x == 0) {
        __threadfence();
        unsigned prev = atomicAdd(&g_arrive, 1u);
        if (prev == NBLK - 1) {
            atomicExch(&g_arrive, 0u);
            __threadfence();
            atomicAdd(&g_gen, 1u);
        } else {
            while (ld_acq(&g_gen) < target) { __nanosleep(64); }
        }
    }
    __syncthreads();
}

__global__ __launch_bounds__(NTHR, 1) void lstm_scan(
    const float* __restrict__ Whh,
    const float* __restrict__ c0,
    float* __restrict__ out)
{
    extern __shared__ char raw[];
    char* sm = (char*)(((uintptr_t)raw + 1023) & ~(uintptr_t)1023);
    const uint32_t sb = smem_u32(sm);

    const int tid  = threadIdx.x;
    const int wid  = tid >> 5;
    const int lane = tid & 31;
    const int j0   = blockIdx.x * 8;

    // --- preload W slice as bf16 hi/lo: row n (0..31) = gate col ---------
    for (int it = 0; it < 128; it++) {
        int e = it * 256 + tid;          // 32768 elements
        int n = e >> 10;
        int k = e & 1023;
        int wrow = (n >> 3) * H_ + j0 + (n & 7);
        float w = __ldg(Whh + (size_t)wrow * H_ + k);
        __nv_bfloat16 hi = __float2bfloat16(w);
        __nv_bfloat16 lo = __float2bfloat16(w - __bfloat162float(hi));
        *(__nv_bfloat16*)(sm + SM_W_HI + n * W_PITCH_B + k * 2) = hi;
        *(__nv_bfloat16*)(sm + SM_W_LO + n * W_PITCH_B + k * 2) = lo;
    }

    // --- c0 into registers: thread owns (b = tid>>2, j = (tid&3)*2 + q) --
    const int cb = tid >> 2;
    const int cj = (tid & 3) * 2;
    float creg[2];
    creg[0] = c0[cb * H_ + j0 + cj];
    creg[1] = c0[cb * H_ + j0 + cj + 1];
    __syncthreads();

    // --- MMA thread mapping ----------------------------------------------
    const int wb = wid & 3;              // batch group (16 rows)
    const int wc = wid >> 2;             // col group (16 cols)
    const int gid = lane >> 2;           // 0..7
    const int tig = lane & 3;            // 0..3

    const uint32_t a_row  = (uint32_t)(wb * 16 + (lane & 15));
    const uint32_t a_kofs = (uint32_t)((lane >> 4) * 8);
    const uint32_t b_row0 = (uint32_t)(wc * 16 + (lane & 7));
    const uint32_t b_kofs = (uint32_t)(((lane >> 3) & 1) * 8);

    for (int t = 0; t < T_; t++) {
        grid_barrier((unsigned)(t + 1));

        const __nv_bfloat16* hh = g_hhi[t & 1];
        const __nv_bfloat16* hl = g_hlo[t & 1];

        float acc0[4] = {0.f, 0.f, 0.f, 0.f};
        float acc1[4] = {0.f, 0.f, 0.f, 0.f};

        // prefetch chunk 0 (each thread: 4 hi + 4 lo uint4 segments)
        uint4 pfh[4], pfl[4];
#pragma unroll
        for (int i = 0; i < 4; i++) {
            int s = tid + i * 256;               // 0..1023
            int row = s >> 4, c16 = s & 15;
            size_t goff = (size_t)row * H_ + c16 * 8;
            pfh[i] = __ldcg((const uint4*)(hh + goff));
            pfl[i] = __ldcg((const uint4*)(hl + goff));
        }

        for (int ch = 0; ch < 8; ch++) {
            // stage regs -> SMEM
#pragma unroll
            for (int i = 0; i < 4; i++) {
                int s = tid + i * 256;
                int row = s >> 4, c16 = s & 15;
                uint32_t doff = (uint32_t)(row * A_PITCH_B + c16 * 16);
                *(uint4*)(sm + SM_A_HI + doff) = pfh[i];
                *(uint4*)(sm + SM_A_LO + doff) = pfl[i];
            }
            __syncthreads();
            if (ch < 7) {
                int kbase = (ch + 1) * 128;
#pragma unroll
                for (int i = 0; i < 4; i++) {
                    int s = tid + i * 256;
                    int row = s >> 4, c16 = s & 15;
                    size_t goff = (size_t)row * H_ + kbase + c16 * 8;
                    pfh[i] = __ldcg((const uint4*)(hh + goff));
                    pfl[i] = __ldcg((const uint4*)(hl + goff));
                }
            }

            // compute: 8 k16 sub-chunks
#pragma unroll
            for (int ks = 0; ks < 8; ks++) {
                unsigned ahi[4], alo[4], bh0[2], bh1[2], bl0[2], bl1[2];
                uint32_t ak = (uint32_t)(ks * 16) + a_kofs;
                uint32_t aaddr = sb + SM_A_HI + a_row * A_PITCH_B + ak * 2;
                ldsm_x4(ahi, aaddr);
                ldsm_x4(alo, aaddr + (SM_A_LO - SM_A_HI));

                uint32_t bk = (uint32_t)(ch * 128 + ks * 16) + b_kofs;
                uint32_t baddr0 = sb + SM_W_HI + b_row0 * W_PITCH_B + bk * 2;
                uint32_t baddr1 = baddr0 + 8u * W_PITCH_B;
                ldsm_x2(bh0, baddr0);
                ldsm_x2(bh1, baddr1);
                ldsm_x2(bl0, baddr0 + (SM_W_LO - SM_W_HI));
                ldsm_x2(bl1, baddr1 + (SM_W_LO - SM_W_HI));

                mma16816(acc0, ahi, bh0);
                mma16816(acc1, ahi, bh1);
                mma16816(acc0, alo, bh0);
                mma16816(acc1, alo, bh1);
                mma16816(acc0, ahi, bl0);
                mma16816(acc1, ahi, bl1);
            }
            __syncthreads();
        }

        // --- exchange: ps[col][batch] ------------------------------------
        float* ps = (float*)(sm + SM_PS);
        {
            int c0i = wc * 16 + tig * 2;
            int r0 = wb * 16 + gid;
            ps[(c0i + 0) * PS_PITCH + r0]     = acc0[0];
            ps[(c0i + 1) * PS_PITCH + r0]     = acc0[1];
            ps[(c0i + 0) * PS_PITCH + r0 + 8] = acc0[2];
            ps[(c0i + 1) * PS_PITCH + r0 + 8] = acc0[3];
            int c1i = c0i + 8;
            ps[(c1i + 0) * PS_PITCH + r0]     = acc1[0];
            ps[(c1i + 1) * PS_PITCH + r0]     = acc1[1];
            ps[(c1i + 0) * PS_PITCH + r0 + 8] = acc1[2];
            ps[(c1i + 1) * PS_PITCH + r0 + 8] = acc1[3];
        }
        __syncthreads();

        // --- gate combine: thread owns (cb, cj), (cb, cj+1) --------------
        const float* xp = g_xpre + ((size_t)t * B_ + cb) * G4 + j0;
        float ht2[2];
#pragma unroll
        for (int q = 0; q < 2; q++) {
            int j = cj + q;
            float pi = ps[j * PS_PITCH + cb]        + __ldcs(xp + j);
            float pf = ps[(8 + j) * PS_PITCH + cb]  + __ldcs(xp + j + H_);
            float po = ps[(16 + j) * PS_PITCH + cb] + __ldcs(xp + j + 2 * H_);
            float pg = ps[(24 + j) * PS_PITCH + cb] + __ldcs(xp + j + 3 * H_);

            float iv = 1.f / (1.f + expf(-pi));
            float fv = 1.f / (1.f + expf(-pf));
            float ov = 1.f / (1.f + expf(-po));
            float gv = tanhf(pg);

            float ct = fv * creg[q] + iv * gv;
            float hv = ov * tanhf(ct);
            creg[q] = ct;
            ht2[q] = hv;
        }

        // output (fp32) + next-h (bf16 hi/lo) stores
        *(float2*)(out + ((size_t)t * B_ + cb) * H_ + j0 + cj) =
            make_float2(ht2[0], ht2[1]);

        __nv_bfloat16 h0b = __float2bfloat16(ht2[0]);
        __nv_bfloat16 h1b = __float2bfloat16(ht2[1]);
        __nv_bfloat16 l0b = __float2bfloat16(ht2[0] - __bfloat162float(h0b));
        __nv_bfloat16 l1b = __float2bfloat16(ht2[1] - __bfloat162float(h1b));
        __nv_bfloat162 hp = __halves2bfloat162(h0b, h1b);
        __nv_bfloat162 lp = __halves2bfloat162(l0b, l1b);
        int hoff = cb * H_ + j0 + cj;
        __stcg((unsigned*)(g_hhi[(t + 1) & 1] + hoff),
               *(unsigned*)&hp);
        __stcg((unsigned*)(g_hlo[(t + 1) & 1] + hoff),
               *(unsigned*)&lp);

        if (t == T_ - 1) {
            *(float2*)(out + (size_t)T_ * B_ * H_ + hoff) =
                make_float2(ht2[0], ht2[1]);
            *(float2*)(out + (size_t)T_ * B_ * H_ + B_ * H_ + hoff) =
                make_float2(creg[0], creg[1]);
        }
        __threadfence();
    }
}

// ---------------------------------------------------------------------------
extern "C" void kernel_launch(void* const* d_in, const int* in_sizes, int n_in,
                              void* d_out, int out_size) {
    const float* input = (const float*)d_in[0];   // [T,B,I]
    const float* h0    = (const float*)d_in[1];   // [1,B,H]
    const float* c0    = (const float*)d_in[2];   // [1,B,H]
    const float* W_ih  = (const float*)d_in[3];   // [4H,I]
    const float* b_ih  = (const float*)d_in[4];   // [4H]
    const float* W_hh  = (const float*)d_in[5];   // [4H,H]
    const float* b_hh  = (const float*)d_in[6];   // [4H]
    float* out = (float*)d_out;

    static int smem_set = 0;
    if (!smem_set) {
        cudaFuncSetAttribute(lstm_scan,
                             cudaFuncAttributeMaxDynamicSharedMemorySize,
                             SMEM_REQ);
        cudaFuncSetAttribute(hmma_xpre,
                             cudaFuncAttributeMaxDynamicSharedMemorySize,
                             XSMEM_REQ);
        smem_set = 1;
    }

    reset_barrier<<<1, 1>>>();
    init_state<<<(B_ * H_ + 255) / 256, 256>>>(h0);

    __nv_bfloat16 *xhi, *xlo, *whi, *wlo;
    cudaGetSymbolAddress((void**)&xhi, g_xhi);
    cudaGetSymbolAddress((void**)&xlo, g_xlo);
    cudaGetSymbolAddress((void**)&whi, g_whi);
    cudaGetSymbolAddress((void**)&wlo, g_wlo);

    cvt_split<<<2048, 256>>>(input, xhi, xlo, M_ * I_ / 4);
    cvt_split<<<1024, 256>>>(W_ih, whi, wlo, G4 * I_ / 4);

    hmma_xpre<<<dim3(G4 / 128, M_ / 128), 256, XSMEM_REQ>>>(b_ih, b_hh);
    lstm_scan<<<NBLK, NTHR, SMEM_REQ>>>(W_hh, c0, out);
}

// round 10
// speedup vs baseline: 3.1867x; 1.0389x over previous
#include <cuda_runtime.h>
#include <cuda_bf16.h>
#include <cstdint>
#include <cstddef>
#include <math.h>

#define T_  512
#define B_  64
#define I_  1024
#define H_  1024
#define G4  4096
#define M_  (T_ * B_)   // 32768
#define NBLK 128
#define NTHR 256

// ---------------------------------------------------------------------------
// Scratch (__device__ globals: allocation-free, harness-legal)
// ---------------------------------------------------------------------------
__device__ float g_xpre[(size_t)M_ * G4];            // [T*B, 4H] pre-activations
__device__ __nv_bfloat16 g_hhi[2][B_ * H_];          // h high bf16 (ping-pong)
__device__ __nv_bfloat16 g_hlo[2][B_ * H_];          // h low  bf16 (ping-pong)
__device__ __nv_bfloat16 g_xhi[(size_t)M_ * I_];     // input hi bf16
__device__ __nv_bfloat16 g_xlo[(size_t)M_ * I_];     // input lo bf16
__device__ __nv_bfloat16 g_whi[(size_t)G4 * I_];     // W_ih hi bf16
__device__ __nv_bfloat16 g_wlo[(size_t)G4 * I_];     // W_ih lo bf16
__device__ unsigned g_gen;
__device__ unsigned g_arrive;

__device__ __forceinline__ unsigned ld_acq(unsigned* p) {
    unsigned v;
    asm volatile("ld.acquire.gpu.u32 %0, [%1];" : "=r"(v) : "l"(p) : "memory");
    return v;
}

// ---------------------------------------------------------------------------
// warp-MMA helpers (base-target PTX: sm_80+, compiles for sm_103)
// ---------------------------------------------------------------------------
__device__ __forceinline__ uint32_t smem_u32(const void* p) {
    uint32_t a;
    asm("{ .reg .u64 t; cvta.to.shared.u64 t, %1; cvt.u32.u64 %0, t; }"
        : "=r"(a) : "l"(p));
    return a;
}
__device__ __forceinline__ void ldsm_x4(unsigned* r, uint32_t addr) {
    asm volatile("ldmatrix.sync.aligned.m8n8.x4.shared.b16 {%0,%1,%2,%3}, [%4];"
                 : "=r"(r[0]), "=r"(r[1]), "=r"(r[2]), "=r"(r[3]) : "r"(addr));
}
__device__ __forceinline__ void mma16816(float* c, const unsigned* a,
                                         const unsigned* b) {
    asm volatile("mma.sync.aligned.m16n8k16.row.col.f32.bf16.bf16.f32 "
                 "{%0,%1,%2,%3}, {%4,%5,%6,%7}, {%8,%9}, {%0,%1,%2,%3};"
                 : "+f"(c[0]), "+f"(c[1]), "+f"(c[2]), "+f"(c[3])
                 : "r"(a[0]), "r"(a[1]), "r"(a[2]), "r"(a[3]),
                   "r"(b[0]), "r"(b[1]));
}
__device__ __forceinline__ void cp_async16(uint32_t daddr, const void* src) {
    asm volatile("cp.async.cg.shared.global [%0], [%1], 16;"
                 :: "r"(daddr), "l"(__cvta_generic_to_global(src)));
}
__device__ __forceinline__ void cp_commit() {
    asm volatile("cp.async.commit_group;");
}
template <int N>
__device__ __forceinline__ void cp_wait() {
    asm volatile("cp.async.wait_group %0;" :: "n"(N));
}

// ---------------------------------------------------------------------------
__global__ void reset_barrier() { g_gen = 0; g_arrive = 0; }

__global__ void init_state(const float* __restrict__ h0) {
    int i = blockIdx.x * blockDim.x + threadIdx.x;
    if (i < B_ * H_) {
        float x = h0[i];
        __nv_bfloat16 hi = __float2bfloat16(x);
        __nv_bfloat16 lo = __float2bfloat16(x - __bfloat162float(hi));
        g_hhi[0][i] = hi;
        g_hlo[0][i] = lo;
    }
}

// split fp32 -> bf16 hi/lo (vectorized, grid-stride)
__global__ void cvt_split(const float* __restrict__ src,
                          __nv_bfloat16* __restrict__ hi,
                          __nv_bfloat16* __restrict__ lo, int n4) {
    for (int i = blockIdx.x * blockDim.x + threadIdx.x; i < n4;
         i += gridDim.x * blockDim.x) {
        float4 v = *(const float4*)(src + (size_t)i * 4);
        __nv_bfloat16 h0 = __float2bfloat16(v.x);
        __nv_bfloat16 h1 = __float2bfloat16(v.y);
        __nv_bfloat16 h2 = __float2bfloat16(v.z);
        __nv_bfloat16 h3 = __float2bfloat16(v.w);
        __nv_bfloat162 hp0 = __halves2bfloat162(h0, h1);
        __nv_bfloat162 hp1 = __halves2bfloat162(h2, h3);
        __nv_bfloat162 lp0 = __halves2bfloat162(
            __float2bfloat16(v.x - __bfloat162float(h0)),
            __float2bfloat16(v.y - __bfloat162float(h1)));
        __nv_bfloat162 lp1 = __halves2bfloat162(
            __float2bfloat16(v.z - __bfloat162float(h2)),
            __float2bfloat16(v.w - __bfloat162float(h3)));
        *(uint2*)(hi + (size_t)i * 4) =
            make_uint2(*(unsigned*)&hp0, *(unsigned*)&hp1);
        *(uint2*)(lo + (size_t)i * 4) =
            make_uint2(*(unsigned*)&lp0, *(unsigned*)&lp1);
    }
}

// ---------------------------------------------------------------------------
// Phase 1: x_pre = input @ W_ih^T + (b_ih + b_hh)  via bf16-split HMMA.
// (byte-identical to the passing R8 kernel)
// ---------------------------------------------------------------------------
#define XPITCH 144
#define XT_SZ  (128 * XPITCH)
#define XSA_HI 0
#define XSA_LO (1 * XT_SZ)
#define XSW_HI (2 * XT_SZ)
#define XSW_LO (3 * XT_SZ)
#define XBUF   (4 * XT_SZ)
#define XS_BIAS (2 * XBUF)
#define XSMEM_REQ (XS_BIAS + 512 + 256)

__device__ __forceinline__ void ldsm_x2(unsigned* r, uint32_t addr) {
    asm volatile("ldmatrix.sync.aligned.m8n8.x2.shared.b16 {%0,%1}, [%2];"
                 : "=r"(r[0]), "=r"(r[1]) : "r"(addr));
}

__global__ __launch_bounds__(256, 1) void hmma_xpre(
    const float* __restrict__ bih, const float* __restrict__ bhh)
{
    extern __shared__ char xsm[];
    const uint32_t sb = smem_u32(xsm);

    const int tid  = threadIdx.x;
    const int wid  = tid >> 5;
    const int lane = tid & 31;
    const int m0 = blockIdx.y * 128;
    const int n0 = blockIdx.x * 128;

    if (tid < 128) {
        ((float*)(xsm + XS_BIAS))[tid] = bih[n0 + tid] + bhh[n0 + tid];
    }

    const int prow = tid >> 1;
    const int pseg0 = (tid & 1) * 4;
    auto load_chunk = [&](int kb, int buf) {
        uint32_t base = sb + (uint32_t)buf * XBUF;
        const __nv_bfloat16* ah = g_xhi + (size_t)(m0 + prow) * I_ + kb;
        const __nv_bfloat16* al = g_xlo + (size_t)(m0 + prow) * I_ + kb;
        const __nv_bfloat16* wh = g_whi + (size_t)(n0 + prow) * I_ + kb;
        const __nv_bfloat16* wl = g_wlo + (size_t)(n0 + prow) * I_ + kb;
        uint32_t ro = (uint32_t)prow * XPITCH;
#pragma unroll
        for (int s = 0; s < 4; s++) {
            int seg = pseg0 + s;
            uint32_t so = ro + (uint32_t)seg * 16;
            cp_async16(base + XSA_HI + so, ah + seg * 8);
            cp_async16(base + XSA_LO + so, al + seg * 8);
            cp_async16(base + XSW_HI + so, wh + seg * 8);
            cp_async16(base + XSW_LO + so, wl + seg * 8);
        }
    };

    const int wm = wid & 3;
    const int wn = wid >> 2;
    const uint32_t a_row  = (uint32_t)(wm * 32 + (lane & 15));
    const uint32_t a_kofs = (uint32_t)((lane >> 4) * 8);
    const uint32_t b_col  = (uint32_t)(wn * 64 + ((lane >> 4) << 3) + (lane & 7));
    const uint32_t b_kofs = (uint32_t)(((lane >> 3) & 1) * 8);

    float acc[2][8][4];
#pragma unroll
    for (int i = 0; i < 2; i++)
#pragma unroll
        for (int j = 0; j < 8; j++)
#pragma unroll
            for (int k = 0; k < 4; k++) acc[i][j][k] = 0.f;

    load_chunk(0, 0);
    cp_commit();

    for (int ch = 0; ch < 16; ch++) {
        if (ch < 15) {
            load_chunk((ch + 1) * 64, (ch + 1) & 1);
            cp_commit();
            cp_wait<1>();
        } else {
            cp_wait<0>();
        }
        __syncthreads();

        uint32_t bufb = sb + (uint32_t)(ch & 1) * XBUF;
#pragma unroll
        for (int ks = 0; ks < 4; ks++) {
            unsigned ahi0[4], ahi1[4], alo0[4], alo1[4];
            uint32_t ak = (uint32_t)(ks * 16) + a_kofs;
            uint32_t a0 = bufb + XSA_HI + a_row * XPITCH + ak * 2;
            uint32_t a1 = a0 + 16u * XPITCH;
            ldsm_x4(ahi0, a0);
            ldsm_x4(ahi1, a1);
            ldsm_x4(alo0, a0 + (XSA_LO - XSA_HI));
            ldsm_x4(alo1, a1 + (XSA_LO - XSA_HI));

#pragma unroll
            for (int ng = 0; ng < 4; ng++) {
                unsigned bh[4], bl[4];
                uint32_t bk = (uint32_t)(ks * 16) + b_kofs;
                uint32_t ba = bufb + XSW_HI + (b_col + ng * 16) * XPITCH + bk * 2;
                ldsm_x4(bh, ba);
                ldsm_x4(bl, ba + (XSW_LO - XSW_HI));

                mma16816(acc[0][ng * 2 + 0], ahi0, bh);
                mma16816(acc[0][ng * 2 + 1], ahi0, bh + 2);
                mma16816(acc[1][ng * 2 + 0], ahi1, bh);
                mma16816(acc[1][ng * 2 + 1], ahi1, bh + 2);
                mma16816(acc[0][ng * 2 + 0], alo0, bh);
                mma16816(acc[0][ng * 2 + 1], alo0, bh + 2);
                mma16816(acc[1][ng * 2 + 0], alo1, bh);
                mma16816(acc[1][ng * 2 + 1], alo1, bh + 2);
                mma16816(acc[0][ng * 2 + 0], ahi0, bl);
                mma16816(acc[0][ng * 2 + 1], ahi0, bl + 2);
                mma16816(acc[1][ng * 2 + 0], ahi1, bl);
                mma16816(acc[1][ng * 2 + 1], ahi1, bl + 2);
            }
        }
        __syncthreads();
    }

    const float* bias = (const float*)(xsm + XS_BIAS);
    const int gid = lane >> 2;
    const int tig = lane & 3;
#pragma unroll
    for (int mi = 0; mi < 2; mi++) {
        int r0 = m0 + wm * 32 + mi * 16 + gid;
#pragma unroll
        for (int f = 0; f < 8; f++) {
            int cl = wn * 64 + f * 8 + tig * 2;
            float b0 = bias[cl], b1 = bias[cl + 1];
            float* p0 = g_xpre + (size_t)r0 * G4 + n0 + cl;
            *(float2*)p0 = make_float2(acc[mi][f][0] + b0, acc[mi][f][1] + b1);
            float* p1 = p0 + (size_t)8 * G4;
            *(float2*)p1 = make_float2(acc[mi][f][2] + b0, acc[mi][f][3] + b1);
        }
    }
}

// ---------------------------------------------------------------------------
// Phase 2: persistent warp-MMA scan (R9: x4 B-loads, cp.async staging,
// register x_pre prefetch, no per-thread fences).
// 128 CTAs x 256 thr (8 warps: 4 batch-groups x 2 col-groups).
// ---------------------------------------------------------------------------
#define W_PITCH_B 2064                 // 1032 bf16
#define A_PITCH_B 272                  // 136 bf16
#define SM_W_HI 0
#define SM_W_LO (SM_W_HI + 32 * W_PITCH_B)          // 66048
#define SM_A0   (SM_W_LO + 32 * W_PITCH_B)          // 132096
#define A_HALF  (64 * A_PITCH_B)                    // 17408
#define A_BUF   (2 * A_HALF)                        // 34816
#define SM_PS   (SM_A0 + 2 * A_BUF)                 // 201728
#define PS_PITCH 68
#define SMEM_NEED (SM_PS + 32 * PS_PITCH * 4)       // 210432
#define SMEM_REQ  (SMEM_NEED + 1024)

__device__ __forceinline__ void grid_barrier(unsigned target) {
    __syncthreads();
    if (threadIdx.x == 0) {
        __threadfence();
        unsigned prev = atomicAdd(&g_arrive, 1u);
        if (prev == NBLK - 1) {
            atomicExch(&g_arrive, 0u);
            __threadfence();
            atomicAdd(&g_gen, 1u);
        } else {
            while (ld_acq(&g_gen) < target) { __nanosleep(32); }
        }
    }
    __syncthreads();
}

__global__ __launch_bounds__(NTHR, 1) void lstm_scan(
    const float* __restrict__ Whh,
    const float* __restrict__ c0,
    float* __restrict__ out)
{
    extern __shared__ char raw[];
    char* sm = (char*)(((uintptr_t)raw + 1023) & ~(uintptr_t)1023);
    const uint32_t sb = smem_u32(sm);

    const int tid  = threadIdx.x;
    const int wid  = tid >> 5;
    const int lane = tid & 31;
    const int j0   = blockIdx.x * 8;

    // --- preload W slice as bf16 hi/lo: row n (0..31) = gate col ---------
    for (int it = 0; it < 128; it++) {
        int e = it * 256 + tid;          // 32768 elements
        int n = e >> 10;
        int k = e & 1023;
        int wrow = (n >> 3) * H_ + j0 + (n & 7);
        float w = __ldg(Whh + (size_t)wrow * H_ + k);
        __nv_bfloat16 hi = __float2bfloat16(w);
        __nv_bfloat16 lo = __float2bfloat16(w - __bfloat162float(hi));
        *(__nv_bfloat16*)(sm + SM_W_HI + n * W_PITCH_B + k * 2) = hi;
        *(__nv_bfloat16*)(sm + SM_W_LO + n * W_PITCH_B + k * 2) = lo;
    }

    // --- c0 into registers: thread owns (b = tid>>2, j = (tid&3)*2 + q) --
    const int cb = tid >> 2;
    const int cj = (tid & 3) * 2;
    float creg[2];
    creg[0] = c0[cb * H_ + j0 + cj];
    creg[1] = c0[cb * H_ + j0 + cj + 1];
    __syncthreads();

    // --- MMA thread mapping ----------------------------------------------
    const int wb = wid & 3;              // batch group (16 rows)
    const int wc = wid >> 2;             // col group (16 cols)
    const int gid = lane >> 2;           // 0..7
    const int tig = lane & 3;            // 0..3

    const uint32_t a_row  = (uint32_t)(wb * 16 + (lane & 15));
    const uint32_t a_kofs = (uint32_t)((lane >> 4) * 8);
    // B x4 mapping: rows wc*16 + {lane<16: 0-7, lane>=16: 8-15}
    const uint32_t b_row  = (uint32_t)(wc * 16 + ((lane >> 4) << 3) + (lane & 7));
    const uint32_t b_kofs = (uint32_t)(((lane >> 3) & 1) * 8);

    // cp.async A staging mapping
    const int prow = tid >> 4;           // 0..15 base row (i adds 16)
    const int pc16 = tid & 15;

    for (int t = 0; t < T_; t++) {
        // x_pre prefetch into registers (no h dependency -> before barrier)
        const float* xp = g_xpre + ((size_t)t * B_ + cb) * G4 + j0 + cj;
        float2 xr0 = __ldcs((const float2*)(xp));
        float2 xr1 = __ldcs((const float2*)(xp + H_));
        float2 xr2 = __ldcs((const float2*)(xp + 2 * H_));
        float2 xr3 = __ldcs((const float2*)(xp + 3 * H_));

        grid_barrier((unsigned)(t + 1));

        const __nv_bfloat16* hh = g_hhi[t & 1];
        const __nv_bfloat16* hl = g_hlo[t & 1];

        float acc0[4] = {0.f, 0.f, 0.f, 0.f};
        float acc1[4] = {0.f, 0.f, 0.f, 0.f};

        // issue chunk 0 -> buf 0
        {
            uint32_t base = sb + SM_A0;
#pragma unroll
            for (int i = 0; i < 4; i++) {
                int row = prow + i * 16;
                uint32_t doff = base + (uint32_t)(row * A_PITCH_B + pc16 * 16);
                size_t goff = (size_t)row * H_ + pc16 * 8;
                cp_async16(doff, hh + goff);
                cp_async16(doff + A_HALF, hl + goff);
            }
            cp_commit();
        }

        for (int ch = 0; ch < 8; ch++) {
            cp_wait<0>();
            __syncthreads();

            if (ch < 7) {
                // issue chunk ch+1 into the other buffer (safe: all threads
                // finished reading it before this barrier)
                uint32_t base = sb + SM_A0 + (uint32_t)((ch + 1) & 1) * A_BUF;
                int kbase = (ch + 1) * 128;
#pragma unroll
                for (int i = 0; i < 4; i++) {
                    int row = prow + i * 16;
                    uint32_t doff = base + (uint32_t)(row * A_PITCH_B + pc16 * 16);
                    size_t goff = (size_t)row * H_ + kbase + pc16 * 8;
                    cp_async16(doff, hh + goff);
                    cp_async16(doff + A_HALF, hl + goff);
                }
                cp_commit();
            }

            uint32_t abase = sb + SM_A0 + (uint32_t)(ch & 1) * A_BUF;
#pragma unroll
            for (int ks = 0; ks < 8; ks++) {
                unsigned ahi[4], alo[4], bh[4], bl[4];
                uint32_t ak = (uint32_t)(ks * 16) + a_kofs;
                uint32_t aaddr = abase + a_row * A_PITCH_B + ak * 2;
                ldsm_x4(ahi, aaddr);
                ldsm_x4(alo, aaddr + A_HALF);

                uint32_t bk = (uint32_t)(ch * 128 + ks * 16) + b_kofs;
                uint32_t baddr = sb + SM_W_HI + b_row * W_PITCH_B + bk * 2;
                ldsm_x4(bh, baddr);
                ldsm_x4(bl, baddr + (SM_W_LO - SM_W_HI));

                mma16816(acc0, ahi, bh);
                mma16816(acc1, ahi, bh + 2);
                mma16816(acc0, alo, bh);
                mma16816(acc1, alo, bh + 2);
                mma16816(acc0, ahi, bl);
                mma16816(acc1, ahi, bl + 2);
            }
        }
        __syncthreads();   // all reads of buf1 done before ps writes reuse... (ps separate; this also closes chunk 7)

        // --- exchange: ps[col][batch] ------------------------------------
        float* ps = (float*)(sm + SM_PS);
        {
            int c0i = wc * 16 + tig * 2;
            int r0 = wb * 16 + gid;
            ps[(c0i + 0) * PS_PITCH + r0]     = acc0[0];
            ps[(c0i + 1) * PS_PITCH + r0]     = acc0[1];
            ps[(c0i + 0) * PS_PITCH + r0 + 8] = acc0[2];
            ps[(c0i + 1) * PS_PITCH + r0 + 8] = acc0[3];
            int c1i = c0i + 8;
            ps[(c1i + 0) * PS_PITCH + r0]     = acc1[0];
            ps[(c1i + 1) * PS_PITCH + r0]     = acc1[1];
            ps[(c1i + 0) * PS_PITCH + r0 + 8] = acc1[2];
            ps[(c1i + 1) * PS_PITCH + r0 + 8] = acc1[3];
        }
        __syncthreads();

        // --- gate combine: thread owns (cb, cj), (cb, cj+1) --------------
        float ht2[2];
#pragma unroll
        for (int q = 0; q < 2; q++) {
            int j = cj + q;
            float xi = q ? xr0.y : xr0.x;
            float xf = q ? xr1.y : xr1.x;
            float xo = q ? xr2.y : xr2.x;
            float xg = q ? xr3.y : xr3.x;
            float pi = ps[j * PS_PITCH + cb]        + xi;
            float pf = ps[(8 + j) * PS_PITCH + cb]  + xf;
            float po = ps[(16 + j) * PS_PITCH + cb] + xo;
            float pg = ps[(24 + j) * PS_PITCH + cb] + xg;

            float iv = 1.f / (1.f + expf(-pi));
            float fv = 1.f / (1.f + expf(-pf));
            float ov = 1.f / (1.f + expf(-po));
            float gv = tanhf(pg);

            float ct = fv * creg[q] + iv * gv;
            float hv = ov * tanhf(ct);
            creg[q] = ct;
            ht2[q] = hv;
        }

        // output (fp32, streaming) + next-h (bf16 hi/lo) stores
        __stcs((float2*)(out + ((size_t)t * B_ + cb) * H_ + j0 + cj),
               make_float2(ht2[0], ht2[1]));

        __nv_bfloat16 h0b = __float2bfloat16(ht2[0]);
        __nv_bfloat16 h1b = __float2bfloat16(ht2[1]);
        __nv_bfloat16 l0b = __float2bfloat16(ht2[0] - __bfloat162float(h0b));
        __nv_bfloat16 l1b = __float2bfloat16(ht2[1] - __bfloat162float(h1b));
        __nv_bfloat162 hp = __halves2bfloat162(h0b, h1b);
        __nv_bfloat162 lp = __halves2bfloat162(l0b, l1b);
        int hoff = cb * H_ + j0 + cj;
        __stcg((unsigned*)(g_hhi[(t + 1) & 1] + hoff), *(unsigned*)&hp);
        __stcg((unsigned*)(g_hlo[(t + 1) & 1] + hoff), *(unsigned*)&lp);

        if (t == T_ - 1) {
            *(float2*)(out + (size_t)T_ * B_ * H_ + hoff) =
                make_float2(ht2[0], ht2[1]);
            *(float2*)(out + (size_t)T_ * B_ * H_ + B_ * H_ + hoff) =
                make_float2(creg[0], creg[1]);
        }
        // release of these h stores happens via the next grid_barrier
        // (syncthreads + tid0 threadfence + atomic  = CG-style release)
    }
}

// ---------------------------------------------------------------------------
extern "C" void kernel_launch(void* const* d_in, const int* in_sizes, int n_in,
                              void* d_out, int out_size) {
    const float* input = (const float*)d_in[0];   // [T,B,I]
    const float* h0    = (const float*)d_in[1];   // [1,B,H]
    const float* c0    = (const float*)d_in[2];   // [1,B,H]
    const float* W_ih  = (const float*)d_in[3];   // [4H,I]
    const float* b_ih  = (const float*)d_in[4];   // [4H]
    const float* W_hh  = (const float*)d_in[5];   // [4H,H]
    const float* b_hh  = (const float*)d_in[6];   // [4H]
    float* out = (float*)d_out;

    static int smem_set = 0;
    if (!smem_set) {
        cudaFuncSetAttribute(lstm_scan,
                             cudaFuncAttributeMaxDynamicSharedMemorySize,
                             SMEM_REQ);
        cudaFuncSetAttribute(hmma_xpre,
                             cudaFuncAttributeMaxDynamicSharedMemorySize,
                             XSMEM_REQ);
        smem_set = 1;
    }

    reset_barrier<<<1, 1>>>();
    init_state<<<(B_ * H_ + 255) / 256, 256>>>(h0);

    __nv_bfloat16 *xhi, *xlo, *whi, *wlo;
    cudaGetSymbolAddress((void**)&xhi, g_xhi);
    cudaGetSymbolAddress((void**)&xlo, g_xlo);
    cudaGetSymbolAddress((void**)&whi, g_whi);
    cudaGetSymbolAddress((void**)&wlo, g_wlo);

    cvt_split<<<2048, 256>>>(input, xhi, xlo, M_ * I_ / 4);
    cvt_split<<<1024, 256>>>(W_ih, whi, wlo, G4 * I_ / 4);

    hmma_xpre<<<dim3(G4 / 128, M_ / 128), 256, XSMEM_REQ>>>(b_ih, b_hh);
    lstm_scan<<<NBLK, NTHR, SMEM_REQ>>>(W_hh, c0, out);
}